// round 15
// baseline (speedup 1.0000x reference)
#include <cuda_runtime.h>
#include <cuda_fp16.h>
#include <math.h>
#include <stdint.h>

#define BATCH 16
#define SEQT  256
#define STATE 1024
#define VOCAB 32000
#define MROWS (SEQT*BATCH)          /* 4096 */
#define LOGITS ((size_t)BATCH*SEQT*VOCAB)
#define NBLK 128

// ------------------------- static device scratch -------------------------
__device__ __half g_WxT[2*3*1024*1024];        // [(j*3+g)*1024 + c][k]  x-part W^T
__device__ __half g_WoT[(size_t)VOCAB*1024];   // [v][k]
__device__ __half g_X0 [(size_t)MROWS*1024];   // embeddings fp16, row = t*16+b
__device__ __half g_Hall[2*(size_t)MROWS*1024];// hidden states per layer, row = t*16+b
__device__ float  g_G  [(size_t)SEQT*3*BATCH*1024]; // [t][gate][c][b]
// batch-minor per-step state
__device__ float  g_hfT[1024*16];              // [c][b] fp32 h
__device__ float  g_zT [1024*16];              // [c][b]
__device__ __half g_hT [1024*16];              // word (c>>1)*16+b = (h[2k],h[2k+1]) for batch b
__device__ __half g_rhT[1024*16];              // same layout, r*h
// mma-fragment-packed recurrent weights
__device__ uint4  gFragA[(size_t)2*NBLK*8*8*32];   // [j][bid128][kh8][ks8][lane32] : z|r
__device__ uint4  gFragB[(size_t)2*64*8*8*32];     // [j][bid64][kh8][ks8][lane32] : n
// barrier state (monotonic across launches/replays)
__device__ volatile unsigned g_arrive[NBLK];   // init barrier (two-hop, proven)
__device__ volatile unsigned g_release;
__device__ volatile unsigned g_arr1[NBLK];     // phase-A arrivals (all 128 blocks)
__device__ volatile unsigned g_arr2[64];       // phase-B arrivals (blocks 0-63)

// ------------------------- small helpers -------------------------
__device__ __forceinline__ uint32_t smem_u32(const void* p){
    return (uint32_t)__cvta_generic_to_shared(p);
}
__device__ __forceinline__ void ldsm_x4(uint32_t* r, uint32_t a){
    asm volatile("ldmatrix.sync.aligned.m8n8.x4.shared.b16 {%0,%1,%2,%3},[%4];"
        : "=r"(r[0]),"=r"(r[1]),"=r"(r[2]),"=r"(r[3]) : "r"(a));
}
__device__ __forceinline__ void mma16816(float* c, const uint32_t* a, uint32_t b0, uint32_t b1){
    asm volatile(
      "mma.sync.aligned.m16n8k16.row.col.f32.f16.f16.f32 "
      "{%0,%1,%2,%3},{%4,%5,%6,%7},{%8,%9},{%0,%1,%2,%3};"
      : "+f"(c[0]),"+f"(c[1]),"+f"(c[2]),"+f"(c[3])
      : "r"(a[0]),"r"(a[1]),"r"(a[2]),"r"(a[3]),"r"(b0),"r"(b1));
}
__device__ __forceinline__ void cp16(void* s, const void* g){
    asm volatile("cp.async.cg.shared.global [%0],[%1],16;" :: "r"(smem_u32(s)), "l"(g));
}
#define CP_COMMIT() asm volatile("cp.async.commit_group;")
#define CP_WAIT1()  asm volatile("cp.async.wait_group 1;")
#define CP_WAIT0()  asm volatile("cp.async.wait_group 0;")

// R3/R10-proven two-hop grid barrier (used once per launch, for h-init).
__device__ __forceinline__ void gridbar(unsigned target){
    __syncthreads();
    if (blockIdx.x == 0){
        unsigned t = threadIdx.x;
        if (t >= 1 && t < NBLK){
            while (g_arrive[t] < target) { }
        }
        __syncthreads();
        if (t == 0){ __threadfence(); g_release = target; }
        __syncthreads();
    } else {
        if (threadIdx.x == 0){
            __threadfence();
            g_arrive[blockIdx.x] = target;
            while (g_release < target) { }
            __threadfence();
        }
        __syncthreads();
    }
}

// ------------------------- weight prep -------------------------
__global__ void wconv_gate(const float* __restrict__ Wz, const float* __restrict__ Wr,
                           const float* __restrict__ Wn){
    int jg = blockIdx.z; int g = jg % 3; int j = jg / 3;
    const float* W = (g==0?Wz:(g==1?Wr:Wn)) + (size_t)j*2048*1024;
    __shared__ float tile[32][33];
    int k0 = blockIdx.x*32, c0 = blockIdx.y*32;
    int tx = threadIdx.x, ty = threadIdx.y;
    for (int i=ty;i<32;i+=8)
        tile[i][tx] = W[(size_t)(k0+i)*1024 + c0 + tx];
    __syncthreads();
    for (int i=ty;i<32;i+=8)
        g_WxT[((size_t)(j*3+g)*1024 + c0 + i)*1024 + k0 + tx] = __float2half(tile[tx][i]);
}

__global__ void wconv_o(const float* __restrict__ Wo){
    __shared__ float tile[32][33];
    int v0 = blockIdx.x*32, k0 = blockIdx.y*32;
    int tx = threadIdx.x, ty = threadIdx.y;
    for (int i=ty;i<32;i+=8)
        tile[i][tx] = Wo[(size_t)(k0+i)*VOCAB + v0 + tx];
    __syncthreads();
    for (int i=ty;i<32;i+=8)
        g_WoT[(size_t)(v0+i)*1024 + k0 + tx] = __float2half(tile[tx][i]);
}

// h-part gate weights -> mma A-fragment order
__global__ void repackA(const float* __restrict__ Wz, const float* __restrict__ Wr){
    int bid = blockIdx.x, kh = blockIdx.y, j = blockIdx.z;
    int tid = threadIdx.x;
    int ks = tid >> 5, lane = tid & 31;
    int r = lane >> 2, q = (lane & 3)*2;
    int gate = bid >> 6;
    int n0 = (bid & 63)*16;
    const float* W = (gate ? Wr : Wz) + (size_t)j*2048*1024;
    int k0 = kh*128 + ks*16;
    size_t rb = (size_t)(1024 + k0 + q)*1024 + n0 + r;
    uint4 o; __half2 t;
    t = __floats2half2_rn(W[rb],              W[rb + 1024]);         o.x = *(uint32_t*)&t;
    t = __floats2half2_rn(W[rb + 8],          W[rb + 1024 + 8]);     o.y = *(uint32_t*)&t;
    t = __floats2half2_rn(W[rb + 8*1024],     W[rb + 9*1024]);       o.z = *(uint32_t*)&t;
    t = __floats2half2_rn(W[rb + 8*1024 + 8], W[rb + 9*1024 + 8]);   o.w = *(uint32_t*)&t;
    gFragA[((((size_t)j*NBLK + bid)*8 + kh)*8 + ks)*32 + lane] = o;
}

__global__ void repackB(const float* __restrict__ Wn){
    int bid = blockIdx.x, kh = blockIdx.y, j = blockIdx.z;
    int tid = threadIdx.x;
    int ks = tid >> 5, lane = tid & 31;
    int r = lane >> 2, q = (lane & 3)*2;
    int n0 = bid*16;
    const float* W = Wn + (size_t)j*2048*1024;
    int k0 = kh*128 + ks*16;
    size_t rb = (size_t)(1024 + k0 + q)*1024 + n0 + r;
    uint4 o; __half2 t;
    t = __floats2half2_rn(W[rb],              W[rb + 1024]);         o.x = *(uint32_t*)&t;
    t = __floats2half2_rn(W[rb + 8],          W[rb + 1024 + 8]);     o.y = *(uint32_t*)&t;
    t = __floats2half2_rn(W[rb + 8*1024],     W[rb + 9*1024]);       o.z = *(uint32_t*)&t;
    t = __floats2half2_rn(W[rb + 8*1024 + 8], W[rb + 9*1024 + 8]);   o.w = *(uint32_t*)&t;
    gFragB[((((size_t)j*64 + bid)*8 + kh)*8 + ks)*32 + lane] = o;
}

__global__ void gather_emb(const int* __restrict__ x, const float* __restrict__ emb){
    int m = blockIdx.x;                 // t*16+b
    int t = m >> 4, b = m & 15;
    int tok = x[b*SEQT + t];
    float4 v = ((const float4*)(emb + (size_t)tok*1024))[threadIdx.x];
    __half2 h0 = __floats2half2_rn(v.x, v.y);
    __half2 h1 = __floats2half2_rn(v.z, v.w);
    size_t o = (size_t)m*1024 + threadIdx.x*4;
    *(__half2*)&g_X0[o]   = h0;
    *(__half2*)&g_X0[o+2] = h1;
}

// ------------------------- gate-precompute GEMM (128x128x32 tiles) -------------------------
__global__ void __launch_bounds__(256) gemm_tc(
    int asel, int jl,
    const float* __restrict__ bias0, const float* __restrict__ bias1,
    const float* __restrict__ bias2)
{
    const __half* A = (asel==0) ? g_X0 : g_Hall + (size_t)(asel-1)*MROWS*1024;
    const __half* BT = g_WxT + (size_t)jl*3*1024*1024;

    __shared__ __half As[2][128][40];
    __shared__ __half Bs[2][128][40];

    const int tid = threadIdx.x;
    const int wid = tid >> 5, lane = tid & 31;
    const int wm = wid >> 2, wn = wid & 3;
    const int bm = blockIdx.y*128, bn = blockIdx.x*128;

    float acc[4][4][4];
    #pragma unroll
    for(int a=0;a<4;a++)
      #pragma unroll
      for(int b=0;b<4;b++){acc[a][b][0]=0;acc[a][b][1]=0;acc[a][b][2]=0;acc[a][b][3]=0;}

    #define GLOAD(buf,kc) do{                                                    \
        _Pragma("unroll")                                                        \
        for(int i=0;i<2;i++){                                                    \
            int cch = tid + i*256;                                               \
            int row = cch>>2, koff=(cch&3)*8;                                    \
            cp16(&As[buf][row][koff], A  + (size_t)(bm+row)*1024 + (kc)*32 + koff); \
            cp16(&Bs[buf][row][koff], BT + (size_t)(bn+row)*1024 + (kc)*32 + koff); \
        } }while(0)

    GLOAD(0,0); CP_COMMIT();

    for (int kc=0; kc<32; kc++){
        int buf = kc & 1;
        if (kc+1 < 32){ GLOAD(buf^1, kc+1); CP_COMMIT(); CP_WAIT1(); }
        else { CP_WAIT0(); }
        __syncthreads();

        #pragma unroll
        for(int ks=0;ks<2;ks++){
            uint32_t af[4][4];
            const int g = lane >> 3;
            #pragma unroll
            for(int mt=0;mt<4;mt++){
                int rr = wm*64 + mt*16 + ((g&1)<<3) + (lane&7);
                int kk = ks*16 + ((g>>1)<<3);
                ldsm_x4(af[mt], smem_u32(&As[buf][rr][kk]));
            }
            uint32_t bf[2][4];
            #pragma unroll
            for(int bt=0;bt<2;bt++){
                int rr = wn*32 + bt*16 + ((g>>1)<<3) + (lane&7);
                int kk = ks*16 + ((g&1)<<3);
                ldsm_x4(bf[bt], smem_u32(&Bs[buf][rr][kk]));
            }
            #pragma unroll
            for(int mt=0;mt<4;mt++)
              #pragma unroll
              for(int bt=0;bt<2;bt++){
                mma16816(acc[mt][bt*2+0], af[mt], bf[bt][0], bf[bt][1]);
                mma16816(acc[mt][bt*2+1], af[mt], bf[bt][2], bf[bt][3]);
              }
        }
        __syncthreads();
    }
    #undef GLOAD

    #pragma unroll
    for(int mt=0;mt<4;mt++){
        int mbase = bm + wm*64 + mt*16 + (lane>>2);
        #pragma unroll
        for(int nt=0;nt<4;nt++){
            int n = bn + wn*32 + nt*8 + (lane&3)*2;
            #pragma unroll
            for(int half_=0;half_<2;half_++){
                int m = mbase + half_*8;
                float v0 = acc[mt][nt][half_*2+0];
                float v1 = acc[mt][nt][half_*2+1];
                int tt = m>>4, b = m&15;
                int g = n>>10, c = n&1023;
                const float* bp = (g==0)?bias0:((g==1)?bias1:bias2);
                size_t o = (size_t)tt*49152 + (size_t)g*16384 + (size_t)c*16 + b;
                g_G[o]    = v0 + bp[jl*1024+c];
                g_G[o+16] = v1 + bp[jl*1024+c+1];
            }
        }
    }
}

// ------------------------- projection GEMM (128M x 256N, kc=16) -------------------------
__global__ void __launch_bounds__(256) gemm_proj(const float* __restrict__ bo,
                                                 float* __restrict__ Cext)
{
    const __half* A  = g_Hall + (size_t)1*MROWS*1024;   // layer-1 hidden states
    const __half* BT = g_WoT;

    __shared__ __half As[2][128][24];
    __shared__ __half Bs[2][256][24];

    const int tid = threadIdx.x;
    const int wid = tid >> 5, lane = tid & 31;
    const int wm = wid >> 2, wn = wid & 3;              // 2 x 4 warps, warp tile 64x64
    const int bm = blockIdx.y*128, bn = blockIdx.x*256;

    float acc[4][8][4];
    #pragma unroll
    for(int a=0;a<4;a++)
      #pragma unroll
      for(int b=0;b<8;b++){acc[a][b][0]=0;acc[a][b][1]=0;acc[a][b][2]=0;acc[a][b][3]=0;}

    #define PLOAD(buf,kc) do{                                                     \
        int arow = tid>>1, akoff=(tid&1)*8;                                       \
        cp16(&As[buf][arow][akoff], A + (size_t)(bm+arow)*1024 + (kc)*16 + akoff);\
        _Pragma("unroll")                                                         \
        for(int i=0;i<2;i++){                                                     \
            int cch = tid + i*256;                                               \
            int brow = cch>>1, bkoff=(cch&1)*8;                                  \
            cp16(&Bs[buf][brow][bkoff], BT + (size_t)(bn+brow)*1024 + (kc)*16 + bkoff); \
        } }while(0)

    PLOAD(0,0); CP_COMMIT();

    for (int kc=0; kc<64; kc++){
        int buf = kc & 1;
        if (kc+1 < 64){ PLOAD(buf^1, kc+1); CP_COMMIT(); CP_WAIT1(); }
        else { CP_WAIT0(); }
        __syncthreads();

        const int g = lane >> 3;
        uint32_t af[4][4];
        #pragma unroll
        for(int mt=0;mt<4;mt++){
            int rr = wm*64 + mt*16 + ((g&1)<<3) + (lane&7);
            int kk = ((g>>1)<<3);
            ldsm_x4(af[mt], smem_u32(&As[buf][rr][kk]));
        }
        uint32_t bf[4][4];
        #pragma unroll
        for(int bt=0;bt<4;bt++){
            int rr = wn*64 + bt*16 + ((g>>1)<<3) + (lane&7);
            int kk = ((g&1)<<3);
            ldsm_x4(bf[bt], smem_u32(&Bs[buf][rr][kk]));
        }
        #pragma unroll
        for(int mt=0;mt<4;mt++)
          #pragma unroll
          for(int bt=0;bt<4;bt++){
            mma16816(acc[mt][bt*2+0], af[mt], bf[bt][0], bf[bt][1]);
            mma16816(acc[mt][bt*2+1], af[mt], bf[bt][2], bf[bt][3]);
          }
        __syncthreads();
    }
    #undef PLOAD

    #pragma unroll
    for(int mt=0;mt<4;mt++){
        int mbase = bm + wm*64 + mt*16 + (lane>>2);
        #pragma unroll
        for(int nt=0;nt<8;nt++){
            int n = bn + wn*64 + nt*8 + (lane&3)*2;
            #pragma unroll
            for(int half_=0;half_<2;half_++){
                int m = mbase + half_*8;
                int tt = m>>4, b = m&15;
                size_t o = ((size_t)b*SEQT + tt)*VOCAB + n;
                float2 out;
                out.x = acc[mt][nt][half_*2+0] + bo[n];
                out.y = acc[mt][nt][half_*2+1] + bo[n+1];
                *(float2*)&Cext[o] = out;
            }
        }
    }
}

// ------------------------- persistent recurrence (one layer) -------------------------
// 128 blocks x 256 threads. Phase A: blocks 0-63 => z cols, 64-127 => r cols.
// Phase B: blocks 0-63 => n cols. Recurrent weights live in registers.
// Role-specialized one-hop barriers: arr1 after A (all arrive, blocks<64 poll),
// arr2 after B (blocks<64 arrive, all poll). Arrive issued from warp 7
// (hi-wid-first priority) so spinning warps 0-3 can't starve the store.
__global__ void __launch_bounds__(256) recur(int jl, float* __restrict__ hfin){
    const int tid = threadIdx.x, bid = blockIdx.x;
    const int wid = tid>>5, lane = tid&31;
    const int r = lane>>2, q = (lane&3)*2;
    __shared__ float red[8][16][17];

    unsigned base = g_release;       // stable pre-barrier; monotonic across launches
    __half* Hout = g_Hall + (size_t)jl*MROWS*1024;

    // recurrent weight fragments -> registers for the whole sequence
    const uint4* fa = gFragA + (((size_t)jl*NBLK + bid)*8 + wid)*8*32;
    uint4 wA[8];
    #pragma unroll
    for(int ks=0;ks<8;ks++) wA[ks] = fa[ks*32 + lane];
    uint4 wB[8];
    if (bid < 64){
        const uint4* fb = gFragB + (((size_t)jl*64 + bid)*8 + wid)*8*32;
        #pragma unroll
        for(int ks=0;ks<8;ks++) wB[ks] = fb[ks*32 + lane];
    }

    { int idx = bid*256 + tid;
      if (idx < 16384){ g_hfT[idx] = 0.f; g_hT[idx] = __float2half(0.f); } }
    gridbar(base + 1);               // proven two-hop init barrier (bumps g_release)

    const uint32_t* h2  = (const uint32_t*)g_hT;
    const uint32_t* rh2 = (const uint32_t*)g_rhT;

    for (int t=0; t<SEQT; t++){
        const float* Gt = g_G + (size_t)t*49152;
        const unsigned T = (base << 8) + (unsigned)t + 1u;   // 256 targets per launch
        // ---------------- phase A : z (bid<64) / r (bid>=64) ----------------
        {
            float acc[2][4];
            #pragma unroll
            for(int b=0;b<2;b++){acc[b][0]=0;acc[b][1]=0;acc[b][2]=0;acc[b][3]=0;}
            #pragma unroll
            for(int ks=0;ks<8;ks++){
                int i0 = (wid*128 + ks*16)/2 + (lane&3);
                uint32_t b00 = __ldcg(&h2[ i0   *16 + r]);
                uint32_t b01 = __ldcg(&h2[(i0+4)*16 + r]);
                uint32_t b10 = __ldcg(&h2[ i0   *16 + 8 + r]);
                uint32_t b11 = __ldcg(&h2[(i0+4)*16 + 8 + r]);
                uint32_t ar[4] = {wA[ks].x, wA[ks].y, wA[ks].z, wA[ks].w};
                mma16816(acc[0], ar, b00, b01);
                mma16816(acc[1], ar, b10, b11);
            }
            #pragma unroll
            for(int bh=0;bh<2;bh++){
                red[wid][r  ][bh*8 + q    ] = acc[bh][0];
                red[wid][r  ][bh*8 + q + 1] = acc[bh][1];
                red[wid][r+8][bh*8 + q    ] = acc[bh][2];
                red[wid][r+8][bh*8 + q + 1] = acc[bh][3];
            }
            __syncthreads();
            {
                int col = tid>>4, b = tid&15;
                float s = 0.f;
                #pragma unroll
                for(int w=0;w<8;w++) s += red[w][col][b];
                if (bid < 64){
                    int c = bid*16 + col;
                    float val = s + Gt[(size_t)c*16 + b];
                    g_zT[c*16 + b] = 1.f/(1.f + expf(-val));
                } else {
                    int c = (bid-64)*16 + col;
                    float val = s + Gt[16384 + (size_t)c*16 + b];
                    float sig = 1.f/(1.f + expf(-val));
                    g_rhT[(c>>1)*32 + b*2 + (c&1)] = __float2half(sig * __ldcg(&g_hfT[c*16 + b]));
                }
            }
        }
        // ---- barrier 1: all arrive; blocks<64 poll ----
        __syncthreads();
        if (tid == 255){ __threadfence(); g_arr1[bid] = T; }
        if (bid < 64){
            if (tid < NBLK){ while (g_arr1[tid] < T) { } }
            __syncthreads();
            if (tid == 0) __threadfence();
            __syncthreads();
            // ---------------- phase B : n ----------------
            {
                float acc[2][4];
                #pragma unroll
                for(int b=0;b<2;b++){acc[b][0]=0;acc[b][1]=0;acc[b][2]=0;acc[b][3]=0;}
                #pragma unroll
                for(int ks=0;ks<8;ks++){
                    int i0 = (wid*128 + ks*16)/2 + (lane&3);
                    uint32_t b00 = __ldcg(&rh2[ i0   *16 + r]);
                    uint32_t b01 = __ldcg(&rh2[(i0+4)*16 + r]);
                    uint32_t b10 = __ldcg(&rh2[ i0   *16 + 8 + r]);
                    uint32_t b11 = __ldcg(&rh2[(i0+4)*16 + 8 + r]);
                    uint32_t ar[4] = {wB[ks].x, wB[ks].y, wB[ks].z, wB[ks].w};
                    mma16816(acc[0], ar, b00, b01);
                    mma16816(acc[1], ar, b10, b11);
                }
                #pragma unroll
                for(int bh=0;bh<2;bh++){
                    red[wid][r  ][bh*8 + q    ] = acc[bh][0];
                    red[wid][r  ][bh*8 + q + 1] = acc[bh][1];
                    red[wid][r+8][bh*8 + q    ] = acc[bh][2];
                    red[wid][r+8][bh*8 + q + 1] = acc[bh][3];
                }
                __syncthreads();
                {
                    int col = tid>>4, b = tid&15;
                    float s = 0.f;
                    #pragma unroll
                    for(int w=0;w<8;w++) s += red[w][col][b];
                    int c = bid*16 + col;
                    float val = s + Gt[32768 + (size_t)c*16 + b];
                    float nv = tanhf(val);
                    float z = __ldcg(&g_zT[c*16 + b]);
                    float h = __ldcg(&g_hfT[c*16 + b]);
                    float hn = (1.f - z)*h + z*nv;
                    g_hfT[c*16 + b] = hn;
                    g_hT[(c>>1)*32 + b*2 + (c&1)] = __float2half(hn);
                    Hout[(size_t)(t*16 + b)*1024 + c] = __float2half(hn);
                    if (t == SEQT-1 && hfin) hfin[b*1024 + c] = hn;
                }
            }
            __syncthreads();
            if (tid == 255){ __threadfence(); g_arr2[bid] = T; }
        }
        // ---- barrier 2: blocks<64 arrived; everyone polls ----
        if (tid < 64){ while (g_arr2[tid] < T) { } }
        __syncthreads();
        if (tid == 0) __threadfence();
        __syncthreads();
    }
}

// ------------------------- launch -------------------------
extern "C" void kernel_launch(void* const* d_in, const int* in_sizes, int n_in,
                              void* d_out, int out_size) {
    const int*   x   = (const int*)  d_in[0];
    const float* emb = (const float*)d_in[1];
    const float* Wz  = (const float*)d_in[2];
    const float* bz  = (const float*)d_in[3];
    const float* Wr  = (const float*)d_in[4];
    const float* br  = (const float*)d_in[5];
    const float* Wn  = (const float*)d_in[6];
    const float* bn  = (const float*)d_in[7];
    const float* Wo  = (const float*)d_in[8];
    const float* bo  = (const float*)d_in[9];
    float* out = (float*)d_out;

    bool has_hfin = ((size_t)out_size >= LOGITS + 2*BATCH*STATE);
    float* hf0 = has_hfin ? out + LOGITS               : nullptr;
    float* hf1 = has_hfin ? out + LOGITS + BATCH*STATE : nullptr;

    gather_emb<<<MROWS, 256>>>(x, emb);
    wconv_gate<<<dim3(32,32,6), dim3(32,8)>>>(Wz, Wr, Wn);
    wconv_o<<<dim3(1000,32), dim3(32,8)>>>(Wo);
    repackA<<<dim3(NBLK,8,2), 256>>>(Wz, Wr);
    repackB<<<dim3(64,8,2), 256>>>(Wn);

    // layer 0
    gemm_tc<<<dim3(24,32), 256>>>(0, 0, bz, br, bn);
    recur<<<NBLK, 256>>>(0, hf0);
    // layer 1
    gemm_tc<<<dim3(24,32), 256>>>(1, 1, bz, br, bn);
    recur<<<NBLK, 256>>>(1, hf1);
    // projection
    gemm_proj<<<dim3(125,32), 256>>>(bo, out);
}

// round 16
// speedup vs baseline: 1.9753x; 1.9753x over previous
#include <cuda_runtime.h>
#include <cuda_fp16.h>
#include <math.h>
#include <stdint.h>

#define BATCH 16
#define SEQT  256
#define STATE 1024
#define VOCAB 32000
#define MROWS (SEQT*BATCH)          /* 4096 */
#define LOGITS ((size_t)BATCH*SEQT*VOCAB)
#define NBLK 128

// ------------------------- static device scratch -------------------------
__device__ __half g_WxT[2*3*1024*1024];        // [(j*3+g)*1024 + c][k]  x-part W^T (j0 used by gemm)
__device__ __half g_WoT[(size_t)VOCAB*1024];   // [v][k]
__device__ __half g_X0 [(size_t)MROWS*1024];   // embeddings fp16, row = t*16+b
__device__ __half g_Hall[2*(size_t)MROWS*1024];// [layer][t*16+b][c]; layer1 half feeds gemm_proj
__device__ float  g_G  [(size_t)SEQT*3*BATCH*1024]; // [t][gate][c][b] layer-0 x-contrib+bias
// batch-minor fp16 state: word (c>>1)*16+b packs (h[2k],h[2k+1])
__device__ __half g_h0T[2][16384];             // double-buffered h0 (parity s&1)
__device__ __half g_h1T[16384];
__device__ __half g_rh0T[16384];
__device__ __half g_rh1T[16384];
// mma-fragment-packed recurrent weights
__device__ uint4  gFragA0[(size_t)NBLK*8*8*32];    // layer0 z|r  (K=1024 h-part)
__device__ uint4  gFragB0[(size_t)64*8*8*32];      // layer0 n
__device__ uint4  gFragA1[(size_t)NBLK*8*16*32];   // layer1 r|z  (K=2048 concat)
__device__ uint4  gFragB1[(size_t)64*8*16*32];     // layer1 n    (K=2048 concat)
// barrier state (monotonic across launches/replays) — R3/R10-proven two-hop
__device__ volatile unsigned g_arrive[NBLK];
__device__ volatile unsigned g_release;

// ------------------------- small helpers -------------------------
__device__ __forceinline__ uint32_t smem_u32(const void* p){
    return (uint32_t)__cvta_generic_to_shared(p);
}
__device__ __forceinline__ void ldsm_x4(uint32_t* r, uint32_t a){
    asm volatile("ldmatrix.sync.aligned.m8n8.x4.shared.b16 {%0,%1,%2,%3},[%4];"
        : "=r"(r[0]),"=r"(r[1]),"=r"(r[2]),"=r"(r[3]) : "r"(a));
}
__device__ __forceinline__ void mma16816(float* c, const uint32_t* a, uint32_t b0, uint32_t b1){
    asm volatile(
      "mma.sync.aligned.m16n8k16.row.col.f32.f16.f16.f32 "
      "{%0,%1,%2,%3},{%4,%5,%6,%7},{%8,%9},{%0,%1,%2,%3};"
      : "+f"(c[0]),"+f"(c[1]),"+f"(c[2]),"+f"(c[3])
      : "r"(a[0]),"r"(a[1]),"r"(a[2]),"r"(a[3]),"r"(b0),"r"(b1));
}
__device__ __forceinline__ void cp16(void* s, const void* g){
    asm volatile("cp.async.cg.shared.global [%0],[%1],16;" :: "r"(smem_u32(s)), "l"(g));
}
#define CP_COMMIT() asm volatile("cp.async.commit_group;")
#define CP_WAIT1()  asm volatile("cp.async.wait_group 1;")
#define CP_WAIT0()  asm volatile("cp.async.wait_group 0;")

// R3/R10-proven two-hop grid barrier — DO NOT CHANGE (all variants failed/slowed).
__device__ __forceinline__ void gridbar(unsigned target){
    __syncthreads();
    if (blockIdx.x == 0){
        unsigned t = threadIdx.x;
        if (t >= 1 && t < NBLK){
            while (g_arrive[t] < target) { }
        }
        __syncthreads();
        if (t == 0){ __threadfence(); g_release = target; }
        __syncthreads();
    } else {
        if (threadIdx.x == 0){
            __threadfence();
            g_arrive[blockIdx.x] = target;
            while (g_release < target) { }
            __threadfence();
        }
        __syncthreads();
    }
}

// ------------------------- weight prep -------------------------
__global__ void wconv_gate(const float* __restrict__ Wz, const float* __restrict__ Wr,
                           const float* __restrict__ Wn){
    int g = blockIdx.z;                       // layer 0 only
    const float* W = (g==0?Wz:(g==1?Wr:Wn));
    __shared__ float tile[32][33];
    int k0 = blockIdx.x*32, c0 = blockIdx.y*32;
    int tx = threadIdx.x, ty = threadIdx.y;
    for (int i=ty;i<32;i+=8)
        tile[i][tx] = W[(size_t)(k0+i)*1024 + c0 + tx];
    __syncthreads();
    for (int i=ty;i<32;i+=8)
        g_WxT[((size_t)g*1024 + c0 + i)*1024 + k0 + tx] = __float2half(tile[tx][i]);
}

__global__ void wconv_o(const float* __restrict__ Wo){
    __shared__ float tile[32][33];
    int v0 = blockIdx.x*32, k0 = blockIdx.y*32;
    int tx = threadIdx.x, ty = threadIdx.y;
    for (int i=ty;i<32;i+=8)
        tile[i][tx] = Wo[(size_t)(k0+i)*VOCAB + v0 + tx];
    __syncthreads();
    for (int i=ty;i<32;i+=8)
        g_WoT[(size_t)(v0+i)*1024 + k0 + tx] = __float2half(tile[tx][i]);
}

// layer0 h-part z|r fragments (proven repack math)
__global__ void repackA0(const float* __restrict__ Wz, const float* __restrict__ Wr){
    int bid = blockIdx.x, kh = blockIdx.y;
    int tid = threadIdx.x;
    int ks = tid >> 5, lane = tid & 31;
    int r = lane >> 2, q = (lane & 3)*2;
    int n0 = (bid & 63)*16;
    const float* W = (bid >> 6) ? Wr : Wz;            // layer 0
    int k0 = kh*128 + ks*16;
    size_t rb = (size_t)(1024 + k0 + q)*1024 + n0 + r;
    uint4 o; __half2 t;
    t = __floats2half2_rn(W[rb],              W[rb + 1024]);         o.x = *(uint32_t*)&t;
    t = __floats2half2_rn(W[rb + 8],          W[rb + 1024 + 8]);     o.y = *(uint32_t*)&t;
    t = __floats2half2_rn(W[rb + 8*1024],     W[rb + 9*1024]);       o.z = *(uint32_t*)&t;
    t = __floats2half2_rn(W[rb + 8*1024 + 8], W[rb + 9*1024 + 8]);   o.w = *(uint32_t*)&t;
    gFragA0[(((size_t)bid*8 + kh)*8 + ks)*32 + lane] = o;
}

__global__ void repackB0(const float* __restrict__ Wn){
    int bid = blockIdx.x, kh = blockIdx.y;
    int tid = threadIdx.x;
    int ks = tid >> 5, lane = tid & 31;
    int r = lane >> 2, q = (lane & 3)*2;
    const float* W = Wn;                              // layer 0
    int k0 = kh*128 + ks*16;
    size_t rb = (size_t)(1024 + k0 + q)*1024 + bid*16 + r;
    uint4 o; __half2 t;
    t = __floats2half2_rn(W[rb],              W[rb + 1024]);         o.x = *(uint32_t*)&t;
    t = __floats2half2_rn(W[rb + 8],          W[rb + 1024 + 8]);     o.y = *(uint32_t*)&t;
    t = __floats2half2_rn(W[rb + 8*1024],     W[rb + 9*1024]);       o.z = *(uint32_t*)&t;
    t = __floats2half2_rn(W[rb + 8*1024 + 8], W[rb + 9*1024 + 8]);   o.w = *(uint32_t*)&t;
    gFragB0[(((size_t)bid*8 + kh)*8 + ks)*32 + lane] = o;
}

// layer1 concat (K=2048: rows 0..1023 = x-part, 1024..2047 = h-part, native W order).
// Blocks <64 get Wr (they compute r1); blocks >=64 get Wz (they compute z1).
__global__ void repackA1(const float* __restrict__ Wz, const float* __restrict__ Wr){
    int bid = blockIdx.x, wid = blockIdx.y;
    int tid = threadIdx.x;
    int ks = tid >> 5, lane = tid & 31;      // ks 0..15
    int r = lane >> 2, q = (lane & 3)*2;
    int n0 = (bid & 63)*16;
    const float* W = ((bid < 64) ? Wr : Wz) + (size_t)2048*1024;   // layer 1
    int k0 = wid*256 + ks*16;
    size_t rb = (size_t)(k0 + q)*1024 + n0 + r;
    uint4 o; __half2 t;
    t = __floats2half2_rn(W[rb],              W[rb + 1024]);         o.x = *(uint32_t*)&t;
    t = __floats2half2_rn(W[rb + 8],          W[rb + 1024 + 8]);     o.y = *(uint32_t*)&t;
    t = __floats2half2_rn(W[rb + 8*1024],     W[rb + 9*1024]);       o.z = *(uint32_t*)&t;
    t = __floats2half2_rn(W[rb + 8*1024 + 8], W[rb + 9*1024 + 8]);   o.w = *(uint32_t*)&t;
    gFragA1[(((size_t)bid*8 + wid)*16 + ks)*32 + lane] = o;
}

__global__ void repackB1(const float* __restrict__ Wn){
    int bid = blockIdx.x, wid = blockIdx.y;
    int tid = threadIdx.x;
    int ks = tid >> 5, lane = tid & 31;
    int r = lane >> 2, q = (lane & 3)*2;
    const float* W = Wn + (size_t)2048*1024;          // layer 1
    int k0 = wid*256 + ks*16;
    size_t rb = (size_t)(k0 + q)*1024 + bid*16 + r;
    uint4 o; __half2 t;
    t = __floats2half2_rn(W[rb],              W[rb + 1024]);         o.x = *(uint32_t*)&t;
    t = __floats2half2_rn(W[rb + 8],          W[rb + 1024 + 8]);     o.y = *(uint32_t*)&t;
    t = __floats2half2_rn(W[rb + 8*1024],     W[rb + 9*1024]);       o.z = *(uint32_t*)&t;
    t = __floats2half2_rn(W[rb + 8*1024 + 8], W[rb + 9*1024 + 8]);   o.w = *(uint32_t*)&t;
    gFragB1[(((size_t)bid*8 + wid)*16 + ks)*32 + lane] = o;
}

__global__ void gather_emb(const int* __restrict__ x, const float* __restrict__ emb){
    int m = blockIdx.x;                 // t*16+b
    int t = m >> 4, b = m & 15;
    int tok = x[b*SEQT + t];
    float4 v = ((const float4*)(emb + (size_t)tok*1024))[threadIdx.x];
    __half2 h0 = __floats2half2_rn(v.x, v.y);
    __half2 h1 = __floats2half2_rn(v.z, v.w);
    size_t o = (size_t)m*1024 + threadIdx.x*4;
    *(__half2*)&g_X0[o]   = h0;
    *(__half2*)&g_X0[o+2] = h1;
}

// ------------------------- layer-0 gate GEMM (128x128x32 tiles) -------------------------
__global__ void __launch_bounds__(256) gemm_tc(
    const float* __restrict__ bias0, const float* __restrict__ bias1,
    const float* __restrict__ bias2)
{
    const __half* A = g_X0;
    const __half* BT = g_WxT;

    __shared__ __half As[2][128][40];
    __shared__ __half Bs[2][128][40];

    const int tid = threadIdx.x;
    const int wid = tid >> 5, lane = tid & 31;
    const int wm = wid >> 2, wn = wid & 3;
    const int bm = blockIdx.y*128, bn = blockIdx.x*128;

    float acc[4][4][4];
    #pragma unroll
    for(int a=0;a<4;a++)
      #pragma unroll
      for(int b=0;b<4;b++){acc[a][b][0]=0;acc[a][b][1]=0;acc[a][b][2]=0;acc[a][b][3]=0;}

    #define GLOAD(buf,kc) do{                                                    \
        _Pragma("unroll")                                                        \
        for(int i=0;i<2;i++){                                                    \
            int cch = tid + i*256;                                               \
            int row = cch>>2, koff=(cch&3)*8;                                    \
            cp16(&As[buf][row][koff], A  + (size_t)(bm+row)*1024 + (kc)*32 + koff); \
            cp16(&Bs[buf][row][koff], BT + (size_t)(bn+row)*1024 + (kc)*32 + koff); \
        } }while(0)

    GLOAD(0,0); CP_COMMIT();

    for (int kc=0; kc<32; kc++){
        int buf = kc & 1;
        if (kc+1 < 32){ GLOAD(buf^1, kc+1); CP_COMMIT(); CP_WAIT1(); }
        else { CP_WAIT0(); }
        __syncthreads();

        #pragma unroll
        for(int ks=0;ks<2;ks++){
            uint32_t af[4][4];
            const int g = lane >> 3;
            #pragma unroll
            for(int mt=0;mt<4;mt++){
                int rr = wm*64 + mt*16 + ((g&1)<<3) + (lane&7);
                int kk = ks*16 + ((g>>1)<<3);
                ldsm_x4(af[mt], smem_u32(&As[buf][rr][kk]));
            }
            uint32_t bf[2][4];
            #pragma unroll
            for(int bt=0;bt<2;bt++){
                int rr = wn*32 + bt*16 + ((g>>1)<<3) + (lane&7);
                int kk = ks*16 + ((g&1)<<3);
                ldsm_x4(bf[bt], smem_u32(&Bs[buf][rr][kk]));
            }
            #pragma unroll
            for(int mt=0;mt<4;mt++)
              #pragma unroll
              for(int bt=0;bt<2;bt++){
                mma16816(acc[mt][bt*2+0], af[mt], bf[bt][0], bf[bt][1]);
                mma16816(acc[mt][bt*2+1], af[mt], bf[bt][2], bf[bt][3]);
              }
        }
        __syncthreads();
    }
    #undef GLOAD

    #pragma unroll
    for(int mt=0;mt<4;mt++){
        int mbase = bm + wm*64 + mt*16 + (lane>>2);
        #pragma unroll
        for(int nt=0;nt<4;nt++){
            int n = bn + wn*32 + nt*8 + (lane&3)*2;
            #pragma unroll
            for(int half_=0;half_<2;half_++){
                int m = mbase + half_*8;
                float v0 = acc[mt][nt][half_*2+0];
                float v1 = acc[mt][nt][half_*2+1];
                int tt = m>>4, b = m&15;
                int g = n>>10, c = n&1023;
                const float* bp = (g==0)?bias0:((g==1)?bias1:bias2);
                size_t o = (size_t)tt*49152 + (size_t)g*16384 + (size_t)c*16 + b;
                g_G[o]    = v0 + bp[c];
                g_G[o+16] = v1 + bp[c+1];
            }
        }
    }
}

// ------------------------- projection GEMM (128M x 256N, kc=16) -------------------------
__global__ void __launch_bounds__(256) gemm_proj(const float* __restrict__ bo,
                                                 float* __restrict__ Cext)
{
    const __half* A  = g_Hall + (size_t)1*MROWS*1024;   // layer-1 hidden states
    const __half* BT = g_WoT;

    __shared__ __half As[2][128][24];
    __shared__ __half Bs[2][256][24];

    const int tid = threadIdx.x;
    const int wid = tid >> 5, lane = tid & 31;
    const int wm = wid >> 2, wn = wid & 3;
    const int bm = blockIdx.y*128, bn = blockIdx.x*256;

    float acc[4][8][4];
    #pragma unroll
    for(int a=0;a<4;a++)
      #pragma unroll
      for(int b=0;b<8;b++){acc[a][b][0]=0;acc[a][b][1]=0;acc[a][b][2]=0;acc[a][b][3]=0;}

    #define PLOAD(buf,kc) do{                                                     \
        int arow = tid>>1, akoff=(tid&1)*8;                                       \
        cp16(&As[buf][arow][akoff], A + (size_t)(bm+arow)*1024 + (kc)*16 + akoff);\
        _Pragma("unroll")                                                         \
        for(int i=0;i<2;i++){                                                     \
            int cch = tid + i*256;                                               \
            int brow = cch>>1, bkoff=(cch&1)*8;                                  \
            cp16(&Bs[buf][brow][bkoff], BT + (size_t)(bn+brow)*1024 + (kc)*16 + bkoff); \
        } }while(0)

    PLOAD(0,0); CP_COMMIT();

    for (int kc=0; kc<64; kc++){
        int buf = kc & 1;
        if (kc+1 < 64){ PLOAD(buf^1, kc+1); CP_COMMIT(); CP_WAIT1(); }
        else { CP_WAIT0(); }
        __syncthreads();

        const int g = lane >> 3;
        uint32_t af[4][4];
        #pragma unroll
        for(int mt=0;mt<4;mt++){
            int rr = wm*64 + mt*16 + ((g&1)<<3) + (lane&7);
            int kk = ((g>>1)<<3);
            ldsm_x4(af[mt], smem_u32(&As[buf][rr][kk]));
        }
        uint32_t bf[4][4];
        #pragma unroll
        for(int bt=0;bt<4;bt++){
            int rr = wn*64 + bt*16 + ((g>>1)<<3) + (lane&7);
            int kk = ((g&1)<<3);
            ldsm_x4(bf[bt], smem_u32(&Bs[buf][rr][kk]));
        }
        #pragma unroll
        for(int mt=0;mt<4;mt++)
          #pragma unroll
          for(int bt=0;bt<4;bt++){
            mma16816(acc[mt][bt*2+0], af[mt], bf[bt][0], bf[bt][1]);
            mma16816(acc[mt][bt*2+1], af[mt], bf[bt][2], bf[bt][3]);
          }
        __syncthreads();
    }
    #undef PLOAD

    #pragma unroll
    for(int mt=0;mt<4;mt++){
        int mbase = bm + wm*64 + mt*16 + (lane>>2);
        #pragma unroll
        for(int nt=0;nt<8;nt++){
            int n = bn + wn*64 + nt*8 + (lane&3)*2;
            #pragma unroll
            for(int half_=0;half_<2;half_++){
                int m = mbase + half_*8;
                int tt = m>>4, b = m&15;
                size_t o = ((size_t)b*SEQT + tt)*VOCAB + n;
                float2 out;
                out.x = acc[mt][nt][half_*2+0] + bo[n];
                out.y = acc[mt][nt][half_*2+1] + bo[n+1];
                *(float2*)&Cext[o] = out;
            }
        }
    }
}

// ------------------------- fused 2-layer pipelined recurrence -------------------------
// 128 blocks x 256 threads, 257 supersteps, 2 barriers each.
// Superstep s: layer0 does t=s (s<256), layer1 does t=s-1 (s>=1).
// Phase A: blocks<64: z0 (reg) + r1->rh1T ; blocks>=64: r0->rh0T + z1 (reg).
// Phase B: blocks<64: n0 + h0 update (h0T[s&1]) ; blocks>=64: n1 + h1 update (+Hall1).
__global__ void __launch_bounds__(256,1) recur_fused(
    const float* __restrict__ bz, const float* __restrict__ br,
    const float* __restrict__ bn,
    float* __restrict__ hfin0, float* __restrict__ hfin1)
{
    const int tid = threadIdx.x, bid = blockIdx.x;
    const int wid = tid>>5, lane = tid&31;
    const int r = lane>>2;
    const int q4 = lane & 3;
    __shared__ float red[8][16][17];

    unsigned base = g_release;
    __half* Hout1 = g_Hall + (size_t)MROWS*1024;

    // fragments -> registers
    const uint4* fa0 = gFragA0 + ((size_t)bid*8 + wid)*8*32 + lane;
    uint4 wA0[8];
    #pragma unroll
    for(int ks=0;ks<8;ks++) wA0[ks] = fa0[ks*32];
    const uint4* fa1 = gFragA1 + ((size_t)bid*8 + wid)*16*32 + lane;
    uint4 wA1[16];
    #pragma unroll
    for(int ks=0;ks<16;ks++) wA1[ks] = fa1[ks*32];
    uint4 wB[16];
    if (bid < 64){
        const uint4* fb = gFragB0 + ((size_t)bid*8 + wid)*8*32 + lane;
        #pragma unroll
        for(int ks=0;ks<8;ks++) wB[ks] = fb[ks*32];
    } else {
        const uint4* fb = gFragB1 + ((size_t)(bid-64)*8 + wid)*16*32 + lane;
        #pragma unroll
        for(int ks=0;ks<16;ks++) wB[ks] = fb[ks*32];
    }

    // per-thread epilogue mapping + persistent state
    const int col = tid>>4, bb = tid&15;
    const int cloc = (bid & 63)*16 + col;
    const int hword = (cloc>>1)*32 + bb*2 + (cloc&1);  // __half index in batch-minor arrays
    float hreg = 0.f;     // h0 (bid<64) / h1 (bid>=64)
    float zreg = 0.f;
    const float bias_zr = (bid < 64) ? br[1024 + cloc] : bz[1024 + cloc];
    const float bias_n1 = bn[1024 + cloc];

    // zero state
    for (int idx = bid*256 + tid; idx < 16384; idx += NBLK*256){
        g_h0T[0][idx] = __float2half(0.f);
        g_h0T[1][idx] = __float2half(0.f);
        g_h1T[idx]    = __float2half(0.f);
    }
    gridbar(base + 1);
    unsigned nb = 2;

    const uint32_t* h1w  = (const uint32_t*)g_h1T;
    const uint32_t* rh0w = (const uint32_t*)g_rh0T;
    const uint32_t* rh1w = (const uint32_t*)g_rh1T;

    for (int s = 0; s <= SEQT; s++){
        const uint32_t* h0p = (const uint32_t*)g_h0T[(s-1)&1];
        const float* Gt = g_G + (size_t)s*49152;
        // ================= phase A =================
        float a0[2][4];
        if (s < SEQT){
            #pragma unroll
            for(int x=0;x<2;x++){a0[x][0]=0;a0[x][1]=0;a0[x][2]=0;a0[x][3]=0;}
            #pragma unroll
            for(int ks=0;ks<8;ks++){
                int i0 = wid*64 + ks*8 + q4;
                uint32_t b00 = __ldcg(&h0p[ i0   *16 + r]);
                uint32_t b01 = __ldcg(&h0p[(i0+4)*16 + r]);
                uint32_t b10 = __ldcg(&h0p[ i0   *16 + 8 + r]);
                uint32_t b11 = __ldcg(&h0p[(i0+4)*16 + 8 + r]);
                uint32_t ar[4] = {wA0[ks].x, wA0[ks].y, wA0[ks].z, wA0[ks].w};
                mma16816(a0[0], ar, b00, b01);
                mma16816(a0[1], ar, b10, b11);
            }
        }
        float a1[2][4];
        if (s >= 1){
            #pragma unroll
            for(int x=0;x<2;x++){a1[x][0]=0;a1[x][1]=0;a1[x][2]=0;a1[x][3]=0;}
            const uint32_t* src = (wid < 4) ? h0p : h1w;
            #pragma unroll
            for(int ks=0;ks<16;ks++){
                int i0 = (wid&3)*128 + ks*8 + q4;
                uint32_t b00 = __ldcg(&src[ i0   *16 + r]);
                uint32_t b01 = __ldcg(&src[(i0+4)*16 + r]);
                uint32_t b10 = __ldcg(&src[ i0   *16 + 8 + r]);
                uint32_t b11 = __ldcg(&src[(i0+4)*16 + 8 + r]);
                uint32_t ar[4] = {wA1[ks].x, wA1[ks].y, wA1[ks].z, wA1[ks].w};
                mma16816(a1[0], ar, b00, b01);
                mma16816(a1[1], ar, b10, b11);
            }
        }
        // reduce pass 1: layer0
        if (s < SEQT){
            const int qq = q4*2;
            #pragma unroll
            for(int bh=0;bh<2;bh++){
                red[wid][r  ][bh*8 + qq    ] = a0[bh][0];
                red[wid][r  ][bh*8 + qq + 1] = a0[bh][1];
                red[wid][r+8][bh*8 + qq    ] = a0[bh][2];
                red[wid][r+8][bh*8 + qq + 1] = a0[bh][3];
            }
            __syncthreads();
            float sum = 0.f;
            #pragma unroll
            for(int w=0;w<8;w++) sum += red[w][col][bb];
            if (bid < 64){
                zreg = 1.f/(1.f + expf(-(sum + Gt[(size_t)cloc*16 + bb])));
            } else {
                float sig = 1.f/(1.f + expf(-(sum + Gt[16384 + (size_t)cloc*16 + bb])));
                float h0v = __half2float(((const __half*)h0p)[hword]);
                g_rh0T[hword] = __float2half(sig * h0v);
            }
            __syncthreads();
        }
        // reduce pass 2: layer1
        if (s >= 1){
            const int qq = q4*2;
            #pragma unroll
            for(int bh=0;bh<2;bh++){
                red[wid][r  ][bh*8 + qq    ] = a1[bh][0];
                red[wid][r  ][bh*8 + qq + 1] = a1[bh][1];
                red[wid][r+8][bh*8 + qq    ] = a1[bh][2];
                red[wid][r+8][bh*8 + qq + 1] = a1[bh][3];
            }
            __syncthreads();
            float sum = 0.f;
            #pragma unroll
            for(int w=0;w<8;w++) sum += red[w][col][bb];
            if (bid < 64){
                float r1 = 1.f/(1.f + expf(-(sum + bias_zr)));
                float h1v = __half2float(g_h1T[hword]);
                g_rh1T[hword] = __float2half(r1 * h1v);
            } else {
                zreg = 1.f/(1.f + expf(-(sum + bias_zr)));
            }
        }
        gridbar(base + nb++);
        // ================= phase B =================
        if (bid < 64){
            if (s < SEQT){
                float acc[2][4];
                #pragma unroll
                for(int x=0;x<2;x++){acc[x][0]=0;acc[x][1]=0;acc[x][2]=0;acc[x][3]=0;}
                #pragma unroll
                for(int ks=0;ks<8;ks++){
                    int i0 = wid*64 + ks*8 + q4;
                    uint32_t b00 = __ldcg(&rh0w[ i0   *16 + r]);
                    uint32_t b01 = __ldcg(&rh0w[(i0+4)*16 + r]);
                    uint32_t b10 = __ldcg(&rh0w[ i0   *16 + 8 + r]);
                    uint32_t b11 = __ldcg(&rh0w[(i0+4)*16 + 8 + r]);
                    uint32_t ar[4] = {wB[ks].x, wB[ks].y, wB[ks].z, wB[ks].w};
                    mma16816(acc[0], ar, b00, b01);
                    mma16816(acc[1], ar, b10, b11);
                }
                const int qq = q4*2;
                #pragma unroll
                for(int bh=0;bh<2;bh++){
                    red[wid][r  ][bh*8 + qq    ] = acc[bh][0];
                    red[wid][r  ][bh*8 + qq + 1] = acc[bh][1];
                    red[wid][r+8][bh*8 + qq    ] = acc[bh][2];
                    red[wid][r+8][bh*8 + qq + 1] = acc[bh][3];
                }
                __syncthreads();
                float sum = 0.f;
                #pragma unroll
                for(int w=0;w<8;w++) sum += red[w][col][bb];
                float nv = tanhf(sum + Gt[32768 + (size_t)cloc*16 + bb]);
                hreg = (1.f - zreg)*hreg + zreg*nv;
                g_h0T[s&1][hword] = __float2half(hreg);
                if (s == SEQT-1 && hfin0) hfin0[bb*1024 + cloc] = hreg;
            }
        } else {
            if (s >= 1){
                float acc[2][4];
                #pragma unroll
                for(int x=0;x<2;x++){acc[x][0]=0;acc[x][1]=0;acc[x][2]=0;acc[x][3]=0;}
                const uint32_t* src = (wid < 4) ? h0p : rh1w;
                #pragma unroll
                for(int ks=0;ks<16;ks++){
                    int i0 = (wid&3)*128 + ks*8 + q4;
                    uint32_t b00 = __ldcg(&src[ i0   *16 + r]);
                    uint32_t b01 = __ldcg(&src[(i0+4)*16 + r]);
                    uint32_t b10 = __ldcg(&src[ i0   *16 + 8 + r]);
                    uint32_t b11 = __ldcg(&src[(i0+4)*16 + 8 + r]);
                    uint32_t ar[4] = {wB[ks].x, wB[ks].y, wB[ks].z, wB[ks].w};
                    mma16816(acc[0], ar, b00, b01);
                    mma16816(acc[1], ar, b10, b11);
                }
                const int qq = q4*2;
                #pragma unroll
                for(int bh=0;bh<2;bh++){
                    red[wid][r  ][bh*8 + qq    ] = acc[bh][0];
                    red[wid][r  ][bh*8 + qq + 1] = acc[bh][1];
                    red[wid][r+8][bh*8 + qq    ] = acc[bh][2];
                    red[wid][r+8][bh*8 + qq + 1] = acc[bh][3];
                }
                __syncthreads();
                float sum = 0.f;
                #pragma unroll
                for(int w=0;w<8;w++) sum += red[w][col][bb];
                float nv = tanhf(sum + bias_n1);
                hreg = (1.f - zreg)*hreg + zreg*nv;
                __half hh = __float2half(hreg);
                g_h1T[hword] = hh;
                Hout1[((size_t)(s-1)*16 + bb)*1024 + cloc] = hh;
                if (s == SEQT && hfin1) hfin1[bb*1024 + cloc] = hreg;
            }
        }
        gridbar(base + nb++);
    }
}

// ------------------------- launch -------------------------
extern "C" void kernel_launch(void* const* d_in, const int* in_sizes, int n_in,
                              void* d_out, int out_size) {
    const int*   x   = (const int*)  d_in[0];
    const float* emb = (const float*)d_in[1];
    const float* Wz  = (const float*)d_in[2];
    const float* bz  = (const float*)d_in[3];
    const float* Wr  = (const float*)d_in[4];
    const float* br  = (const float*)d_in[5];
    const float* Wn  = (const float*)d_in[6];
    const float* bn  = (const float*)d_in[7];
    const float* Wo  = (const float*)d_in[8];
    const float* bo  = (const float*)d_in[9];
    float* out = (float*)d_out;

    bool has_hfin = ((size_t)out_size >= LOGITS + 2*BATCH*STATE);
    float* hf0 = has_hfin ? out + LOGITS               : nullptr;
    float* hf1 = has_hfin ? out + LOGITS + BATCH*STATE : nullptr;

    gather_emb<<<MROWS, 256>>>(x, emb);
    wconv_gate<<<dim3(32,32,3), dim3(32,8)>>>(Wz, Wr, Wn);
    wconv_o<<<dim3(1000,32), dim3(32,8)>>>(Wo);
    repackA0<<<dim3(NBLK,8), 256>>>(Wz, Wr);
    repackB0<<<dim3(64,8), 256>>>(Wn);
    repackA1<<<dim3(NBLK,8), 512>>>(Wz, Wr);
    repackB1<<<dim3(64,8), 512>>>(Wn);

    // layer-0 gate precompute
    gemm_tc<<<dim3(24,32), 256>>>(bz, br, bn);
    // fused pipelined recurrence (both layers)
    recur_fused<<<NBLK, 256>>>(bz, br, bn, hf0, hf1);
    // projection
    gemm_proj<<<dim3(125,32), 256>>>(bo, out);
}